// round 3
// baseline (speedup 1.0000x reference)
#include <cuda_runtime.h>
#include <math.h>

// Problem dims
#define BB 32
#define TT 2048
#define HH 16
#define HD 128
#define CC 2048          // H*HD
#define TCH 128          // attention T-chunk
#define NCH 16           // T / TCH
#define ATT_SCALE 0.08838834764831845f  // 1/sqrt(128)

// ---------------- scratch (device globals; no allocation allowed) ----------------
__device__ float g_h[BB * CC];             // LN1 out
__device__ float g_qkv[BB * 3 * CC];       // qkv
__device__ float g_part[6291456];          // split-K partials (max 32 chunks * 32 * 6144)
__device__ float g_ao[BB * CC];            // attention output (B, C)
__device__ float g_x1[BB * CC];            // x + attn_proj
__device__ float g_h2[BB * CC];            // LN2 out
__device__ float g_fc[BB * 4 * CC];        // gelu(fc)
__device__ float g_pm[BB * HH * NCH];      // partial max
__device__ float g_pl[BB * HH * NCH];      // partial sumexp
__device__ float g_po[BB * HH * NCH * HD]; // partial weighted V sums

#define BUF_H   0
#define BUF_QKV 1
#define BUF_AO  3
#define BUF_X1  4
#define BUF_H2  5
#define BUF_FC  6
__device__ __forceinline__ float* dev_buf(int id) {
    switch (id) {
        case BUF_H:   return g_h;
        case BUF_QKV: return g_qkv;
        case BUF_AO:  return g_ao;
        case BUF_X1:  return g_x1;
        case BUF_H2:  return g_h2;
        case BUF_FC:  return g_fc;
    }
    return nullptr;
}

// ---------------- f32x2 packed-FMA helpers (Blackwell sm_100+) ----------------
__device__ __forceinline__ unsigned long long f32x2_pack(float lo, float hi) {
    unsigned long long r;
    asm("mov.b64 %0, {%1, %2};" : "=l"(r) : "f"(lo), "f"(hi));
    return r;
}
__device__ __forceinline__ void f32x2_fma(unsigned long long& d,
                                          unsigned long long a,
                                          unsigned long long b) {
    asm("fma.rn.f32x2 %0, %1, %2, %3;" : "=l"(d) : "l"(a), "l"(b), "l"(d));
}
__device__ __forceinline__ float2 f32x2_unpack(unsigned long long v) {
    float lo, hi;
    asm("mov.b64 {%0, %1}, %2;" : "=f"(lo), "=f"(hi) : "l"(v));
    return make_float2(lo, hi);
}

// ---------------- LayerNorm: one block per row ----------------
__global__ __launch_bounds__(256) void ln_kernel(const float* __restrict__ x_ext,
                                                 int src_id,
                                                 const float* __restrict__ sc,
                                                 const float* __restrict__ bi,
                                                 int dst_id) {
    const float* x = (src_id < 0) ? x_ext : dev_buf(src_id);
    float* y = dev_buf(dst_id);
    const int b = blockIdx.x, tid = threadIdx.x;
    const int warp = tid >> 5, lane = tid & 31;
    const float* xr = x + b * CC;
    float v[8];
    float s = 0.f;
#pragma unroll
    for (int i = 0; i < 8; i++) { v[i] = xr[tid + i * 256]; s += v[i]; }
    __shared__ float red[8];
#pragma unroll
    for (int o = 16; o > 0; o >>= 1) s += __shfl_xor_sync(0xffffffffu, s, o);
    if (lane == 0) red[warp] = s;
    __syncthreads();
    s = red[0];
#pragma unroll
    for (int i = 1; i < 8; i++) s += red[i];
    const float mean = s * (1.f / (float)CC);
    float q = 0.f;
#pragma unroll
    for (int i = 0; i < 8; i++) { float d = v[i] - mean; q += d * d; }
    __syncthreads();
#pragma unroll
    for (int o = 16; o > 0; o >>= 1) q += __shfl_xor_sync(0xffffffffu, q, o);
    if (lane == 0) red[warp] = q;
    __syncthreads();
    q = red[0];
#pragma unroll
    for (int i = 1; i < 8; i++) q += red[i];
    const float r = rsqrtf(q * (1.f / (float)CC) + 1e-5f);
#pragma unroll
    for (int i = 0; i < 8; i++) {
        const int n = tid + i * 256;
        y[b * CC + n] = (v[i] - mean) * r * sc[n] + bi[n];
    }
}

// ---------------- split-K GEMM partial: g_part[chunk][32][N] = A[32,Kchunk] @ W ----------------
// 256 threads = 128 col-threads (4 cols each) x 2 row-halves (16 rows each).
// A tile (32x32) staged in SMEM as duplicated f32x2 pairs; inner loop per kk is
// 1 LDG.128 (W) + 8 LDS.128 (broadcast) + 32 FFMA2.
__global__ __launch_bounds__(256) void gemm_partial(int a_id,
                                                    const float* __restrict__ W,
                                                    int K, int N, int kchunk) {
    const float* A = dev_buf(a_id);
    __shared__ unsigned long long sD[32 * 32];
    const int tid = threadIdx.x;
    const int half = tid >> 7;          // 0/1: row half
    const int ct = tid & 127;           // column thread
    const int n0 = blockIdx.x * 512 + ct * 4;
    const int kb0 = blockIdx.y * kchunk;
    unsigned long long accA[16], accB[16];
#pragma unroll
    for (int m = 0; m < 16; m++) { accA[m] = 0ULL; accB[m] = 0ULL; }

    const int lm = tid >> 3;         // 0..31  (row for staging)
    const int lk = (tid & 7) << 2;   // 0,4,...,28

    for (int ks = 0; ks < kchunk; ks += 32) {
        const int kb = kb0 + ks;
        const float4 a4 = *(const float4*)&A[lm * K + kb + lk];
        sD[(lk + 0) * 32 + lm] = f32x2_pack(a4.x, a4.x);
        sD[(lk + 1) * 32 + lm] = f32x2_pack(a4.y, a4.y);
        sD[(lk + 2) * 32 + lm] = f32x2_pack(a4.z, a4.z);
        sD[(lk + 3) * 32 + lm] = f32x2_pack(a4.w, a4.w);
        __syncthreads();
#pragma unroll 4
        for (int kk = 0; kk < 32; kk++) {
            const float4 w4 = *(const float4*)&W[(size_t)(kb + kk) * N + n0];
            const unsigned long long wp0 = f32x2_pack(w4.x, w4.y);
            const unsigned long long wp1 = f32x2_pack(w4.z, w4.w);
            const unsigned long long* row = &sD[kk * 32 + half * 16];
#pragma unroll
            for (int m2 = 0; m2 < 8; m2++) {
                const ulonglong2 p = *(const ulonglong2*)&row[m2 * 2];
                f32x2_fma(accA[m2 * 2 + 0], p.x, wp0);
                f32x2_fma(accB[m2 * 2 + 0], p.x, wp1);
                f32x2_fma(accA[m2 * 2 + 1], p.y, wp0);
                f32x2_fma(accB[m2 * 2 + 1], p.y, wp1);
            }
        }
        __syncthreads();
    }
#pragma unroll
    for (int m = 0; m < 16; m++) {
        const int rg = blockIdx.y * 32 + half * 16 + m;
        const float2 a = f32x2_unpack(accA[m]);
        const float2 b = f32x2_unpack(accB[m]);
        *(float4*)&g_part[(size_t)rg * N + n0] = make_float4(a.x, a.y, b.x, b.y);
    }
}

// ---------------- split-K reduce + bias (+gelu) (+residual), float4 + MLP=4 ----------------
__device__ __forceinline__ float gelu1(float s) {
    const float x3 = s * s * s;
    return 0.5f * s * (1.f + tanhf(0.7978845608028654f * (s + 0.044715f * x3)));
}
__global__ __launch_bounds__(256) void reduce_ep(const float* __restrict__ bias,
                                                 const float* __restrict__ resid_ext,
                                                 int resid_id,
                                                 float* __restrict__ dst_ext,
                                                 int dst_id,
                                                 int N, int nchunk, int do_gelu) {
    const float* resid = (resid_id < 0) ? resid_ext : dev_buf(resid_id);
    float* dst = (dst_id < 0) ? dst_ext : dev_buf(dst_id);
    const int i4 = blockIdx.x * 256 + threadIdx.x;
    const int N4 = N >> 2;
    const int total4 = 32 * N4;
    if (i4 >= total4) return;
    const int n4 = i4 % N4;
    const float4* p = ((const float4*)g_part) + i4;
    float4 s0 = make_float4(0, 0, 0, 0), s1 = s0, s2 = s0, s3 = s0;
    for (int c = 0; c < nchunk; c += 4) {  // nchunk always multiple of 4
        const float4 a = p[(size_t)(c + 0) * total4];
        const float4 b = p[(size_t)(c + 1) * total4];
        const float4 cc = p[(size_t)(c + 2) * total4];
        const float4 d = p[(size_t)(c + 3) * total4];
        s0.x += a.x; s0.y += a.y; s0.z += a.z; s0.w += a.w;
        s1.x += b.x; s1.y += b.y; s1.z += b.z; s1.w += b.w;
        s2.x += cc.x; s2.y += cc.y; s2.z += cc.z; s2.w += cc.w;
        s3.x += d.x; s3.y += d.y; s3.z += d.z; s3.w += d.w;
    }
    float4 s = make_float4(s0.x + s1.x + s2.x + s3.x, s0.y + s1.y + s2.y + s3.y,
                           s0.z + s1.z + s2.z + s3.z, s0.w + s1.w + s2.w + s3.w);
    const float4 bi = ((const float4*)bias)[n4];
    s.x += bi.x; s.y += bi.y; s.z += bi.z; s.w += bi.w;
    if (do_gelu) { s.x = gelu1(s.x); s.y = gelu1(s.y); s.z = gelu1(s.z); s.w = gelu1(s.w); }
    if (resid) {
        const float4 r = ((const float4*)resid)[i4];
        s.x += r.x; s.y += r.y; s.z += r.z; s.w += r.w;
    }
    ((float4*)dst)[i4] = s;
}

// ---------------- copy k_new / v_new outputs from qkv (float4) ----------------
__global__ void copy_kv(float* __restrict__ ok, float* __restrict__ ov) {
    const int i4 = blockIdx.x * 256 + threadIdx.x;
    if (i4 >= BB * CC / 4) return;
    const int b = i4 >> 9, c4 = i4 & 511;       // CC/4 = 512
    const float4* q4 = (const float4*)g_qkv;
    ((float4*)ok)[i4] = q4[b * 1536 + 512 + c4];
    ((float4*)ov)[i4] = q4[b * 1536 + 1024 + c4];
}

// ---------------- flash-decode attention partial over one T chunk ----------------
// 128 threads. Phase 1: each warp handles 32 t as 8 iterations of 4 t;
// lane = 8*sub + d8 : sub selects t within group, d8 covers 16 floats of HD.
// -> 4 independent LDG.128 per lane per iteration, 3-stage shfl reduction.
__global__ __launch_bounds__(128) void attn_partial(const float* __restrict__ Kc,
                                                    const float* __restrict__ Vc,
                                                    const int* __restrict__ pos) {
    const int c = blockIdx.x, h = blockIdx.y, b = blockIdx.z;
    const int p = pos[b];
    const int tbase = c * TCH;
    if (tbase > p) return;
    const int tcnt = min(TCH, p + 1 - tbase);
    __shared__ float s[TCH];
    __shared__ float red[4];
    const int tid = threadIdx.x, warp = tid >> 5, lane = tid & 31;
    const int sub = lane >> 3, d8 = lane & 7;

    // Preload q (16 floats per lane), pre-scaled by 1/sqrt(HD)
    float4 qa[4];
    {
        const float* qp = &g_qkv[b * 3 * CC + h * HD + d8 * 16];
#pragma unroll
        for (int j = 0; j < 4; j++) {
            qa[j] = *(const float4*)&qp[j * 4];
            qa[j].x *= ATT_SCALE; qa[j].y *= ATT_SCALE;
            qa[j].z *= ATT_SCALE; qa[j].w *= ATT_SCALE;
        }
    }

    // Phase 1: scores
#pragma unroll
    for (int it = 0; it < 8; it++) {
        const int t = warp * 32 + it * 4 + sub;
        float d = 0.f;
        if (t < tcnt) {
            const float* kp =
                &Kc[((size_t)((b * TT + tbase + t) * HH + h)) * HD + d8 * 16];
#pragma unroll
            for (int j = 0; j < 4; j++) {
                const float4 kv = *(const float4*)&kp[j * 4];
                d += qa[j].x * kv.x + qa[j].y * kv.y + qa[j].z * kv.z + qa[j].w * kv.w;
            }
        }
        d += __shfl_xor_sync(0xffffffffu, d, 4);
        d += __shfl_xor_sync(0xffffffffu, d, 2);
        d += __shfl_xor_sync(0xffffffffu, d, 1);
        if (d8 == 0 && t < tcnt) s[t] = d;
    }
    __syncthreads();

    // Phase 2: softmax over s[0..tcnt)
    const float sv = (tid < tcnt) ? s[tid] : -3.4e38f;
    float mx = sv;
#pragma unroll
    for (int o = 16; o > 0; o >>= 1) mx = fmaxf(mx, __shfl_xor_sync(0xffffffffu, mx, o));
    if (lane == 0) red[warp] = mx;
    __syncthreads();
    mx = fmaxf(fmaxf(red[0], red[1]), fmaxf(red[2], red[3]));
    const float e = (tid < tcnt) ? __expf(sv - mx) : 0.f;
    __syncthreads();                 // all reads of red[] and s[] done
    s[tid] = e;                      // e = 0 for invalid t -> phase 3 is branch-light
    float sum = e;
#pragma unroll
    for (int o = 16; o > 0; o >>= 1) sum += __shfl_xor_sync(0xffffffffu, sum, o);
    if (lane == 0) red[warp] = sum;
    __syncthreads();
    sum = red[0] + red[1] + red[2] + red[3];

    // Phase 3: weighted V accumulation; thread = head-dim element. Unroll 8 -> MLP 8.
    float acc = 0.f;
    const float* vp = &Vc[((size_t)((b * TT + tbase) * HH + h)) * HD + tid];
    const int t_end = (tcnt + 7) & ~7;
    for (int t = 0; t < t_end; t += 8) {
        float v0 = vp[(size_t)(t + 0) * CC];
        float v1 = vp[(size_t)(t + 1) * CC];
        float v2 = vp[(size_t)(t + 2) * CC];
        float v3 = vp[(size_t)(t + 3) * CC];
        float v4 = vp[(size_t)(t + 4) * CC];
        float v5 = vp[(size_t)(t + 5) * CC];
        float v6 = vp[(size_t)(t + 6) * CC];
        float v7 = vp[(size_t)(t + 7) * CC];
        acc += s[t] * v0 + s[t + 1] * v1 + s[t + 2] * v2 + s[t + 3] * v3;
        acc += s[t + 4] * v4 + s[t + 5] * v5 + s[t + 6] * v6 + s[t + 7] * v7;
    }

    const int idx = (b * HH + h) * NCH + c;
    g_po[idx * HD + tid] = acc;
    if (tid == 0) { g_pm[idx] = mx; g_pl[idx] = sum; }
}

// ---------------- combine flash-decode partials -> g_ao ----------------
__global__ __launch_bounds__(128) void attn_combine(const int* __restrict__ pos) {
    const int bh = blockIdx.x;
    const int b = bh >> 4, h = bh & 15;
    const int nch = (pos[b] >> 7) + 1;  // valid chunks (TCH=128)
    const int tid = threadIdx.x;
    float gm = -3.4e38f;
    for (int c = 0; c < nch; c++) gm = fmaxf(gm, g_pm[bh * NCH + c]);
    float l = 0.f, acc = 0.f;
    for (int c = 0; c < nch; c++) {
        const float w = __expf(g_pm[bh * NCH + c] - gm);
        l += g_pl[bh * NCH + c] * w;
        acc += g_po[(bh * NCH + c) * HD + tid] * w;
    }
    g_ao[b * CC + h * HD + tid] = acc / l;
}

// ---------------- launch: kernel launches ONLY ----------------
extern "C" void kernel_launch(void* const* d_in, const int* in_sizes, int n_in,
                              void* d_out, int out_size) {
    const float* x           = (const float*)d_in[0];
    const float* prev_k      = (const float*)d_in[1];
    const float* prev_v      = (const float*)d_in[2];
    const int*   pos         = (const int*)d_in[3];
    const float* ln1_scale   = (const float*)d_in[4];
    const float* ln1_bias    = (const float*)d_in[5];
    const float* w_attn      = (const float*)d_in[6];
    const float* b_attn      = (const float*)d_in[7];
    const float* w_attn_proj = (const float*)d_in[8];
    const float* b_attn_proj = (const float*)d_in[9];
    const float* ln2_scale   = (const float*)d_in[10];
    const float* ln2_bias    = (const float*)d_in[11];
    const float* w_fc        = (const float*)d_in[12];
    const float* b_fc        = (const float*)d_in[13];
    const float* w_mlp_proj  = (const float*)d_in[14];
    const float* b_mlp_proj  = (const float*)d_in[15];
    float* out = (float*)d_out;   // [x (65536) | k_new (65536) | v_new (65536)]

    // 1. LN1: x -> g_h
    ln_kernel<<<32, 256>>>(x, -1, ln1_scale, ln1_bias, BUF_H);
    // 2. qkv = g_h @ w_attn + b  (K=2048, N=6144; 32 K-chunks of 64)
    gemm_partial<<<dim3(12, 32), 256>>>(BUF_H, w_attn, 2048, 6144, 64);
    reduce_ep<<<(32 * 6144 / 4 + 255) / 256, 256>>>(b_attn, nullptr, -1, nullptr,
                                                    BUF_QKV, 6144, 32, 0);
    // 3. flash-decode attention -> g_ao   (placed at launch idx 3 for ncu)
    attn_partial<<<dim3(NCH, HH, BB), 128>>>(prev_k, prev_v, pos);
    attn_combine<<<BB * HH, 128>>>(pos);
    // 4. emit k_new / v_new outputs
    copy_kv<<<(BB * CC / 4 + 255) / 256, 256>>>(out + 65536, out + 131072);
    // 5. attn_proj + residual(x): g_ao @ w_attn_proj + b + x -> g_x1
    //    (K=2048, N=2048; 64 K-chunks of 32)
    gemm_partial<<<dim3(4, 64), 256>>>(BUF_AO, w_attn_proj, 2048, 2048, 32);
    reduce_ep<<<(32 * 2048 / 4 + 255) / 256, 256>>>(b_attn_proj, x, -1, nullptr,
                                                    BUF_X1, 2048, 64, 0);
    // 6. LN2: g_x1 -> g_h2
    ln_kernel<<<32, 256>>>(nullptr, BUF_X1, ln2_scale, ln2_bias, BUF_H2);
    // 7. fc + gelu: g_h2 @ w_fc -> gelu -> g_fc  (K=2048, N=8192; 16 K-chunks of 128)
    gemm_partial<<<dim3(16, 16), 256>>>(BUF_H2, w_fc, 2048, 8192, 128);
    reduce_ep<<<(32 * 8192 / 4 + 255) / 256, 256>>>(b_fc, nullptr, -1, nullptr,
                                                    BUF_FC, 8192, 16, 1);
    // 8. mlp_proj + residual(g_x1) -> out x  (K=8192, N=2048; 64 K-chunks of 128)
    gemm_partial<<<dim3(4, 64), 256>>>(BUF_FC, w_mlp_proj, 8192, 2048, 128);
    reduce_ep<<<(32 * 2048 / 4 + 255) / 256, 256>>>(b_mlp_proj, nullptr, BUF_X1,
                                                    out, -1, 2048, 64, 0);
}

// round 5
// speedup vs baseline: 1.4863x; 1.4863x over previous
#include <cuda_runtime.h>
#include <cuda_bf16.h>
#include <math.h>
#include <stdint.h>

// Problem dims
#define BB 32
#define TT 2048
#define HH 16
#define HD 128
#define CC 2048
#define TCH 128
#define NCH 16
#define ATT_SCALE 0.08838834764831845f

// ---------------- scratch (device globals) ----------------
__device__ float g_q[BB * CC];                 // q (fp32, for attention)
__device__ float g_x1[BB * CC];                // x + attn_proj (fp32)
__device__ float g_part[2097152];              // split-K partials (max 32*32*2048)
__device__ __nv_bfloat16 g_ah[BB * 8192];      // activation hi (GEMM A side)
__device__ __nv_bfloat16 g_al[BB * 8192];      // activation lo
__device__ float g_pm[BB * HH * NCH];
__device__ float g_pl[BB * HH * NCH];
__device__ float g_po[BB * HH * NCH * HD];

// ---------------- helpers ----------------
__device__ __forceinline__ uint32_t smem_u32(const void* p) {
    return (uint32_t)__cvta_generic_to_shared(p);
}
// pack two floats as bf16x2: low half = lo, high half = hi
__device__ __forceinline__ uint32_t cvt2_bf16(float lo, float hi) {
    uint32_t r;
    asm("cvt.rn.bf16x2.f32 %0, %1, %2;" : "=r"(r) : "f"(hi), "f"(lo));
    return r;
}
__device__ __forceinline__ void ldmA(uint32_t* r, uint32_t addr) {
    asm volatile("ldmatrix.sync.aligned.m8n8.x4.shared.b16 {%0,%1,%2,%3}, [%4];"
                 : "=r"(r[0]), "=r"(r[1]), "=r"(r[2]), "=r"(r[3]) : "r"(addr));
}
__device__ __forceinline__ void ldmB(uint32_t* r, uint32_t addr) {
    asm volatile("ldmatrix.sync.aligned.m8n8.x4.trans.shared.b16 {%0,%1,%2,%3}, [%4];"
                 : "=r"(r[0]), "=r"(r[1]), "=r"(r[2]), "=r"(r[3]) : "r"(addr));
}
__device__ __forceinline__ void mma_bf16(float* c, const uint32_t* a, const uint32_t* b) {
    asm volatile(
        "mma.sync.aligned.m16n8k16.row.col.f32.bf16.bf16.f32 "
        "{%0,%1,%2,%3}, {%4,%5,%6,%7}, {%8,%9}, {%0,%1,%2,%3};"
        : "+f"(c[0]), "+f"(c[1]), "+f"(c[2]), "+f"(c[3])
        : "r"(a[0]), "r"(a[1]), "r"(a[2]), "r"(a[3]), "r"(b[0]), "r"(b[1]));
}
__device__ __forceinline__ float gelu1(float s) {
    const float x3 = s * s * s;
    return 0.5f * s * (1.f + tanhf(0.7978845608028654f * (s + 0.044715f * x3)));
}

// SMEM layout for gemm_tc (bytes). B rows: 256 bf16 + 8 pad = 528B; A rows: 32+8 = 80B.
#define SMB_H 0
#define SMB_L 16896
#define SMA_H 33792
#define SMA_L 36352
#define SM_GEMM 38912

// ============ tensor-core GEMM partial: g_part[kchunk-blk][32][Nout slice] ============
// Block tile: 32 (all batch rows, MMA M=2x16) x 256 (W cols). K in 32-steps.
// A = activations (bf16 hi/lo, pre-split in g_ah/g_al). B = W, converted fp32->bf16
// hi/lo during SMEM staging. 3-term split: Ah*Bh + Ah*Bl + Al*Bh.
__global__ __launch_bounds__(256) void gemm_tc(const float* __restrict__ W,
                                               int Ktot, int Nout, int kchunk) {
    extern __shared__ unsigned char sm[];
    const uint32_t sb = smem_u32(sm);
    const int tid = threadIdx.x, lane = tid & 31, wp = tid >> 5;
    const int n0 = blockIdx.x * 256;
    const int kg0 = blockIdx.y * kchunk;

    float acc[2][4][4];
#pragma unroll
    for (int mt = 0; mt < 2; mt++)
#pragma unroll
        for (int nt = 0; nt < 4; nt++)
#pragma unroll
            for (int i = 0; i < 4; i++) acc[mt][nt][i] = 0.f;

    // A staging coords: 128 threads stage hi, 128 stage lo; 16B per thread.
    const int ar = tid & 127;
    const int arow = ar >> 2, achk = ar & 3;
    const __nv_bfloat16* Asrc = ((tid < 128) ? g_ah : g_al) + (size_t)arow * Ktot;
    const int adst = ((tid < 128) ? SMA_H : SMA_L) + arow * 80 + achk * 16;

    // ldmatrix fragment base offsets
    const uint32_t aoff = (uint32_t)((lane & 15) * 80 + ((lane >> 4) << 4));
    const uint32_t boff = (uint32_t)((lane & 15) * 528 + wp * 64 + ((lane >> 4) << 4));

    for (int kg = kg0; kg < kg0 + kchunk; kg += 32) {
        // ---- stage A tile (32x32 bf16, hi+lo) ----
        *(uint4*)(sm + adst) = *(const uint4*)(Asrc + kg + achk * 8);
        // ---- stage B tile = W[kg..kg+32)[n0..n0+256), convert to bf16 hi/lo ----
        const float* Wp = W + (size_t)kg * Nout + n0;
#pragma unroll
        for (int r = 0; r < 8; r++) {
            const int idx = tid + r * 256;
            const int k = idx >> 6, c4 = idx & 63;
            const float4 wv = *(const float4*)(Wp + (size_t)k * Nout + c4 * 4);
            const uint32_t h01 = cvt2_bf16(wv.x, wv.y);
            const uint32_t h23 = cvt2_bf16(wv.z, wv.w);
            const float l0 = wv.x - __uint_as_float(h01 << 16);
            const float l1 = wv.y - __uint_as_float(h01 & 0xffff0000u);
            const float l2 = wv.z - __uint_as_float(h23 << 16);
            const float l3 = wv.w - __uint_as_float(h23 & 0xffff0000u);
            const uint32_t l01 = cvt2_bf16(l0, l1);
            const uint32_t l23 = cvt2_bf16(l2, l3);
            const int d = k * 528 + c4 * 8;
            *(uint2*)(sm + SMB_H + d) = make_uint2(h01, h23);
            *(uint2*)(sm + SMB_L + d) = make_uint2(l01, l23);
        }
        __syncthreads();
        // ---- compute: 2 k16-halves ----
#pragma unroll
        for (int kh = 0; kh < 2; kh++) {
            uint32_t ah0[4], ah1[4], al0[4], al1[4];
            ldmA(ah0, sb + SMA_H + aoff + kh * 32);
            ldmA(ah1, sb + SMA_H + aoff + kh * 32 + 1280);
            ldmA(al0, sb + SMA_L + aoff + kh * 32);
            ldmA(al1, sb + SMA_L + aoff + kh * 32 + 1280);
            uint32_t bh[8], bl[8];
            ldmB(bh + 0, sb + SMB_H + boff + kh * 8448);
            ldmB(bh + 4, sb + SMB_H + boff + kh * 8448 + 32);
            ldmB(bl + 0, sb + SMB_L + boff + kh * 8448);
            ldmB(bl + 4, sb + SMB_L + boff + kh * 8448 + 32);
#pragma unroll
            for (int nt = 0; nt < 4; nt++) {
                const uint32_t* bhn = &bh[nt * 2];
                const uint32_t* bln = &bl[nt * 2];
                mma_bf16(acc[0][nt], ah0, bhn);
                mma_bf16(acc[0][nt], ah0, bln);
                mma_bf16(acc[0][nt], al0, bhn);
                mma_bf16(acc[1][nt], ah1, bhn);
                mma_bf16(acc[1][nt], ah1, bln);
                mma_bf16(acc[1][nt], al1, bhn);
            }
        }
        __syncthreads();
    }
    // ---- write partials ----
#pragma unroll
    for (int mt = 0; mt < 2; mt++)
#pragma unroll
        for (int nt = 0; nt < 4; nt++) {
            const int m = mt * 16 + (lane >> 2);
            const int n = n0 + wp * 32 + nt * 8 + (lane & 3) * 2;
            float* base = &g_part[((size_t)blockIdx.y * 32 + m) * Nout + n];
            *(float2*)base = make_float2(acc[mt][nt][0], acc[mt][nt][1]);
            *(float2*)(base + (size_t)8 * Nout) = make_float2(acc[mt][nt][2], acc[mt][nt][3]);
        }
}

// ---------------- LayerNorm -> bf16 hi/lo activations ----------------
__global__ __launch_bounds__(256) void ln_kernel(const float* __restrict__ x_ext,
                                                 int use_x1, int row0,
                                                 const float* __restrict__ sc,
                                                 const float* __restrict__ bi) {
    const float* x = use_x1 ? g_x1 : x_ext;
    const int b = blockIdx.x + row0, tid = threadIdx.x;
    const int warp = tid >> 5, lane = tid & 31;
    const float* xr = x + b * CC;
    float v[8];
    float s = 0.f;
#pragma unroll
    for (int i = 0; i < 8; i++) { v[i] = xr[tid + i * 256]; s += v[i]; }
    __shared__ float red[8];
#pragma unroll
    for (int o = 16; o > 0; o >>= 1) s += __shfl_xor_sync(0xffffffffu, s, o);
    if (lane == 0) red[warp] = s;
    __syncthreads();
    s = red[0];
#pragma unroll
    for (int i = 1; i < 8; i++) s += red[i];
    const float mean = s * (1.f / (float)CC);
    float q = 0.f;
#pragma unroll
    for (int i = 0; i < 8; i++) { float d = v[i] - mean; q += d * d; }
    __syncthreads();
#pragma unroll
    for (int o = 16; o > 0; o >>= 1) q += __shfl_xor_sync(0xffffffffu, q, o);
    if (lane == 0) red[warp] = q;
    __syncthreads();
    q = red[0];
#pragma unroll
    for (int i = 1; i < 8; i++) q += red[i];
    const float r = rsqrtf(q * (1.f / (float)CC) + 1e-5f);
#pragma unroll
    for (int i = 0; i < 8; i++) {
        const int n = tid + i * 256;
        const float val = (v[i] - mean) * r * sc[n] + bi[n];
        const __nv_bfloat16 hb = __float2bfloat16_rn(val);
        g_ah[b * CC + n] = hb;
        g_al[b * CC + n] = __float2bfloat16_rn(val - __bfloat162float(hb));
    }
}

// ---------------- reduce: qkv (bias + scatter q/k/v) ----------------
__global__ __launch_bounds__(256) void red_qkv(const float* __restrict__ bias,
                                               float* __restrict__ ok,
                                               float* __restrict__ ov) {
    const int i4 = blockIdx.x * 256 + threadIdx.x;   // < 49152
    const int row = i4 / 1536, n4 = i4 % 1536;
    const float4* p = ((const float4*)g_part) + i4;
    float4 s = make_float4(0, 0, 0, 0);
#pragma unroll
    for (int c = 0; c < 8; c++) {
        const float4 a = p[(size_t)c * 49152];
        s.x += a.x; s.y += a.y; s.z += a.z; s.w += a.w;
    }
    const float4 bi = ((const float4*)bias)[n4];
    s.x += bi.x; s.y += bi.y; s.z += bi.z; s.w += bi.w;
    if (n4 < 512)       ((float4*)g_q)[row * 512 + n4] = s;
    else if (n4 < 1024) ((float4*)ok)[row * 512 + n4 - 512] = s;
    else                ((float4*)ov)[row * 512 + n4 - 1024] = s;
}

// ---------------- reduce: bias + residual -> fp32 (proj & mlp) ----------------
__global__ __launch_bounds__(256) void red_resid(const float* __restrict__ bias,
                                                 const float* __restrict__ resid_ext,
                                                 int resid_x1,
                                                 float* __restrict__ dst_ext,
                                                 int dst_x1, int nchunk) {
    const float* resid = resid_x1 ? g_x1 : resid_ext;
    float* dst = dst_x1 ? g_x1 : dst_ext;
    const int i4 = blockIdx.x * 256 + threadIdx.x;   // < 16384 (N=2048)
    const int n4 = i4 & 511;
    const float4* p = ((const float4*)g_part) + i4;
    float4 s0 = make_float4(0, 0, 0, 0), s1 = s0;
    for (int c = 0; c < nchunk; c += 2) {
        const float4 a = p[(size_t)c * 16384];
        const float4 b = p[(size_t)(c + 1) * 16384];
        s0.x += a.x; s0.y += a.y; s0.z += a.z; s0.w += a.w;
        s1.x += b.x; s1.y += b.y; s1.z += b.z; s1.w += b.w;
    }
    const float4 bi = ((const float4*)bias)[n4];
    const float4 r = ((const float4*)resid)[i4];
    float4 s = make_float4(s0.x + s1.x + bi.x + r.x, s0.y + s1.y + bi.y + r.y,
                           s0.z + s1.z + bi.z + r.z, s0.w + s1.w + bi.w + r.w);
    ((float4*)dst)[i4] = s;
}

// ---------------- reduce: bias + gelu -> bf16 hi/lo (fc) ----------------
__global__ __launch_bounds__(256) void red_gelu(const float* __restrict__ bias) {
    const int i4 = blockIdx.x * 256 + threadIdx.x;   // < 65536 (N=8192)
    const int n4 = i4 & 2047;
    const float4* p = ((const float4*)g_part) + i4;
    float4 s = make_float4(0, 0, 0, 0);
#pragma unroll
    for (int c = 0; c < 4; c++) {
        const float4 a = p[(size_t)c * 65536];
        s.x += a.x; s.y += a.y; s.z += a.z; s.w += a.w;
    }
    const float4 bi = ((const float4*)bias)[n4];
    const float g0 = gelu1(s.x + bi.x), g1 = gelu1(s.y + bi.y);
    const float g2 = gelu1(s.z + bi.z), g3 = gelu1(s.w + bi.w);
    const uint32_t h01 = cvt2_bf16(g0, g1), h23 = cvt2_bf16(g2, g3);
    const float l0 = g0 - __uint_as_float(h01 << 16);
    const float l1 = g1 - __uint_as_float(h01 & 0xffff0000u);
    const float l2 = g2 - __uint_as_float(h23 << 16);
    const float l3 = g3 - __uint_as_float(h23 & 0xffff0000u);
    ((uint2*)g_ah)[i4] = make_uint2(h01, h23);
    ((uint2*)g_al)[i4] = make_uint2(cvt2_bf16(l0, l1), cvt2_bf16(l2, l3));
}

// ---------------- flash-decode attention (90us @ 77% spec, unchanged) ----------------
__global__ __launch_bounds__(128) void attn_partial(const float* __restrict__ Kc,
                                                    const float* __restrict__ Vc,
                                                    const int* __restrict__ pos) {
    const int c = blockIdx.x, h = blockIdx.y, b = blockIdx.z;
    const int p = pos[b];
    const int tbase = c * TCH;
    if (tbase > p) return;
    const int tcnt = min(TCH, p + 1 - tbase);
    __shared__ float s[TCH];
    __shared__ float red[4];
    const int tid = threadIdx.x, warp = tid >> 5, lane = tid & 31;
    const int sub = lane >> 3, d8 = lane & 7;

    float4 qa[4];
    {
        const float* qp = &g_q[b * CC + h * HD + d8 * 16];
#pragma unroll
        for (int j = 0; j < 4; j++) {
            qa[j] = *(const float4*)&qp[j * 4];
            qa[j].x *= ATT_SCALE; qa[j].y *= ATT_SCALE;
            qa[j].z *= ATT_SCALE; qa[j].w *= ATT_SCALE;
        }
    }
#pragma unroll
    for (int it = 0; it < 8; it++) {
        const int t = warp * 32 + it * 4 + sub;
        float d = 0.f;
        if (t < tcnt) {
            const float* kp =
                &Kc[((size_t)((b * TT + tbase + t) * HH + h)) * HD + d8 * 16];
#pragma unroll
            for (int j = 0; j < 4; j++) {
                const float4 kv = *(const float4*)&kp[j * 4];
                d += qa[j].x * kv.x + qa[j].y * kv.y + qa[j].z * kv.z + qa[j].w * kv.w;
            }
        }
        d += __shfl_xor_sync(0xffffffffu, d, 4);
        d += __shfl_xor_sync(0xffffffffu, d, 2);
        d += __shfl_xor_sync(0xffffffffu, d, 1);
        if (d8 == 0 && t < tcnt) s[t] = d;
    }
    __syncthreads();

    const float sv = (tid < tcnt) ? s[tid] : -3.4e38f;
    float mx = sv;
#pragma unroll
    for (int o = 16; o > 0; o >>= 1) mx = fmaxf(mx, __shfl_xor_sync(0xffffffffu, mx, o));
    if (lane == 0) red[warp] = mx;
    __syncthreads();
    mx = fmaxf(fmaxf(red[0], red[1]), fmaxf(red[2], red[3]));
    const float e = (tid < tcnt) ? __expf(sv - mx) : 0.f;
    __syncthreads();
    s[tid] = e;
    float sum = e;
#pragma unroll
    for (int o = 16; o > 0; o >>= 1) sum += __shfl_xor_sync(0xffffffffu, sum, o);
    if (lane == 0) red[warp] = sum;
    __syncthreads();
    sum = red[0] + red[1] + red[2] + red[3];

    float acc = 0.f;
    const float* vp = &Vc[((size_t)((b * TT + tbase) * HH + h)) * HD + tid];
    const int t_end = (tcnt + 7) & ~7;
    for (int t = 0; t < t_end; t += 8) {
        float v0 = vp[(size_t)(t + 0) * CC];
        float v1 = vp[(size_t)(t + 1) * CC];
        float v2 = vp[(size_t)(t + 2) * CC];
        float v3 = vp[(size_t)(t + 3) * CC];
        float v4 = vp[(size_t)(t + 4) * CC];
        float v5 = vp[(size_t)(t + 5) * CC];
        float v6 = vp[(size_t)(t + 6) * CC];
        float v7 = vp[(size_t)(t + 7) * CC];
        acc += s[t] * v0 + s[t + 1] * v1 + s[t + 2] * v2 + s[t + 3] * v3;
        acc += s[t + 4] * v4 + s[t + 5] * v5 + s[t + 6] * v6 + s[t + 7] * v7;
    }
    const int idx = (b * HH + h) * NCH + c;
    g_po[idx * HD + tid] = acc;
    if (tid == 0) { g_pm[idx] = mx; g_pl[idx] = sum; }
}

// combine -> bf16 hi/lo activations (input of proj GEMM)
__global__ __launch_bounds__(128) void attn_combine(const int* __restrict__ pos) {
    const int bh = blockIdx.x;
    const int b = bh >> 4, h = bh & 15;
    const int nch = (pos[b] >> 7) + 1;
    const int tid = threadIdx.x;
    float gm = -3.4e38f;
    for (int c = 0; c < nch; c++) gm = fmaxf(gm, g_pm[bh * NCH + c]);
    float l = 0.f, acc = 0.f;
    for (int c = 0; c < nch; c++) {
        const float w = __expf(g_pm[bh * NCH + c] - gm);
        l += g_pl[bh * NCH + c] * w;
        acc += g_po[(bh * NCH + c) * HD + tid] * w;
    }
    const float val = acc / l;
    const int di = b * CC + h * HD + tid;
    const __nv_bfloat16 hb = __float2bfloat16_rn(val);
    g_ah[di] = hb;
    g_al[di] = __float2bfloat16_rn(val - __bfloat162float(hb));
}

// ---------------- launch: kernel launches ONLY ----------------
extern "C" void kernel_launch(void* const* d_in, const int* in_sizes, int n_in,
                              void* d_out, int out_size) {
    const float* x           = (const float*)d_in[0];
    const float* prev_k      = (const float*)d_in[1];
    const float* prev_v      = (const float*)d_in[2];
    const int*   pos         = (const int*)d_in[3];
    const float* ln1_scale   = (const float*)d_in[4];
    const float* ln1_bias    = (const float*)d_in[5];
    const float* w_attn      = (const float*)d_in[6];
    const float* b_attn      = (const float*)d_in[7];
    const float* w_attn_proj = (const float*)d_in[8];
    const float* b_attn_proj = (const float*)d_in[9];
    const float* ln2_scale   = (const float*)d_in[10];
    const float* ln2_bias    = (const float*)d_in[11];
    const float* w_fc        = (const float*)d_in[12];
    const float* b_fc        = (const float*)d_in[13];
    const float* w_mlp_proj  = (const float*)d_in[14];
    const float* b_mlp_proj  = (const float*)d_in[15];
    float* out = (float*)d_out;   // [x | k_new | v_new]

    // 0-2. LN1 in 3 launches (puts gemm_tc(qkv) at launch idx 3 for ncu)
    ln_kernel<<<11, 256>>>(x, 0, 0, ln1_scale, ln1_bias);
    ln_kernel<<<11, 256>>>(x, 0, 11, ln1_scale, ln1_bias);
    ln_kernel<<<10, 256>>>(x, 0, 22, ln1_scale, ln1_bias);
    // 3. qkv GEMM: K=2048, N=6144; 24 n-blocks x 8 k-chunks(256)
    gemm_tc<<<dim3(24, 8), 256, SM_GEMM>>>(w_attn, 2048, 6144, 256);
    // 4. reduce qkv: bias + scatter q / k_new / v_new
    red_qkv<<<192, 256>>>(b_attn, out + 65536, out + 131072);
    // 5-6. attention
    attn_partial<<<dim3(NCH, HH, BB), 128>>>(prev_k, prev_v, pos);
    attn_combine<<<BB * HH, 128>>>(pos);
    // 7. attn proj GEMM: K=2048, N=2048; 8 x 16 k-chunks(128)
    gemm_tc<<<dim3(8, 16), 256, SM_GEMM>>>(w_attn_proj, 2048, 2048, 128);
    // 8. reduce: bias + resid(x) -> g_x1
    red_resid<<<64, 256>>>(b_attn_proj, x, 0, nullptr, 1, 16);
    // 9. LN2: g_x1 -> hi/lo
    ln_kernel<<<32, 256>>>(nullptr, 1, 0, ln2_scale, ln2_bias);
    // 10. fc GEMM: K=2048, N=8192; 32 x 4 k-chunks(512)
    gemm_tc<<<dim3(32, 4), 256, SM_GEMM>>>(w_fc, 2048, 8192, 512);
    // 11. reduce: bias + gelu -> hi/lo
    red_gelu<<<256, 256>>>(b_fc);
    // 12. mlp proj GEMM: K=8192, N=2048; 8 x 32 k-chunks(256)
    gemm_tc<<<dim3(8, 32), 256, SM_GEMM>>>(w_mlp_proj, 8192, 2048, 256);
    // 13. reduce: bias + resid(g_x1) -> out
    red_resid<<<64, 256>>>(b_mlp_proj, nullptr, 1, out, 0, 32);
}

// round 8
// speedup vs baseline: 1.5822x; 1.0645x over previous
#include <cuda_runtime.h>
#include <cuda_bf16.h>
#include <math.h>
#include <stdint.h>

// Problem dims
#define BB 32
#define TT 2048
#define HH 16
#define HD 128
#define CC 2048
#define TCH 128
#define NCH 16
#define ATT_SCALE 0.08838834764831845f

// ---------------- scratch (device globals) ----------------
__device__ float g_q[BB * CC];                 // q (fp32, for attention)
__device__ float g_x1[BB * CC];                // x + attn_proj (fp32)
__device__ float g_part[4194304];              // split-K partials (max 64*32*2048)
__device__ __nv_bfloat16 g_ah[BB * 8192];      // activation hi (GEMM A side)
__device__ __nv_bfloat16 g_al[BB * 8192];      // activation lo
__device__ float g_pm[BB * HH * NCH];
__device__ float g_pl[BB * HH * NCH];
__device__ float g_po[BB * HH * NCH * HD];

// ---------------- helpers ----------------
__device__ __forceinline__ uint32_t smem_u32(const void* p) {
    return (uint32_t)__cvta_generic_to_shared(p);
}
// pack two floats as bf16x2: low half = lo, high half = hi
__device__ __forceinline__ uint32_t cvt2_bf16(float lo, float hi) {
    uint32_t r;
    asm("cvt.rn.bf16x2.f32 %0, %1, %2;" : "=r"(r) : "f"(hi), "f"(lo));
    return r;
}
__device__ __forceinline__ void ldmA(uint32_t* r, uint32_t addr) {
    asm volatile("ldmatrix.sync.aligned.m8n8.x4.shared.b16 {%0,%1,%2,%3}, [%4];"
                 : "=r"(r[0]), "=r"(r[1]), "=r"(r[2]), "=r"(r[3]) : "r"(addr));
}
__device__ __forceinline__ void ldmB(uint32_t* r, uint32_t addr) {
    asm volatile("ldmatrix.sync.aligned.m8n8.x4.trans.shared.b16 {%0,%1,%2,%3}, [%4];"
                 : "=r"(r[0]), "=r"(r[1]), "=r"(r[2]), "=r"(r[3]) : "r"(addr));
}
__device__ __forceinline__ void mma_bf16(float* c, const uint32_t* a, const uint32_t* b) {
    asm volatile(
        "mma.sync.aligned.m16n8k16.row.col.f32.bf16.bf16.f32 "
        "{%0,%1,%2,%3}, {%4,%5,%6,%7}, {%8,%9}, {%0,%1,%2,%3};"
        : "+f"(c[0]), "+f"(c[1]), "+f"(c[2]), "+f"(c[3])
        : "r"(a[0]), "r"(a[1]), "r"(a[2]), "r"(a[3]), "r"(b[0]), "r"(b[1]));
}
__device__ __forceinline__ float gelu1(float s) {
    const float x3 = s * s * s;
    return 0.5f * s * (1.f + tanhf(0.7978845608028654f * (s + 0.044715f * x3)));
}

// SMEM layout for gemm_tc (bytes). B rows: 256 bf16 + 8 pad = 528B; A rows: 32+8 = 80B.
#define SMB_H 0
#define SMB_L 16896
#define SMA_H 33792
#define SMA_L 36352
#define SM_GEMM 38912

// ============ tensor-core GEMM partial: g_part[kchunk-blk][32][Nout slice] ============
// Block tile: 32 (all batch rows, MMA M=2x16) x 256 (W cols). K in 32-steps.
// A = activations (bf16 hi/lo, pre-split). B = W, fp32->bf16 hi/lo during staging.
// 3-term split: Ah*Bh + Ah*Bl + Al*Bh. max-3-blocks/SM to hide staging latency.
__global__ __launch_bounds__(256, 3) void gemm_tc(const float* __restrict__ W,
                                                  int Ktot, int Nout, int kchunk) {
    extern __shared__ unsigned char sm[];
    const uint32_t sb = smem_u32(sm);
    const int tid = threadIdx.x, lane = tid & 31, wp = tid >> 5;
    const int n0 = blockIdx.x * 256;
    const int kg0 = blockIdx.y * kchunk;

    float acc[2][4][4];
#pragma unroll
    for (int mt = 0; mt < 2; mt++)
#pragma unroll
        for (int nt = 0; nt < 4; nt++)
#pragma unroll
            for (int i = 0; i < 4; i++) acc[mt][nt][i] = 0.f;

    // A staging coords: 128 threads stage hi, 128 stage lo; 16B per thread.
    const int ar = tid & 127;
    const int arow = ar >> 2, achk = ar & 3;
    const __nv_bfloat16* Asrc = ((tid < 128) ? g_ah : g_al) + (size_t)arow * Ktot;
    const int adst = ((tid < 128) ? SMA_H : SMA_L) + arow * 80 + achk * 16;

    // ldmatrix fragment base offsets
    const uint32_t aoff = (uint32_t)((lane & 15) * 80 + ((lane >> 4) << 4));
    const uint32_t boff = (uint32_t)((lane & 15) * 528 + wp * 64 + ((lane >> 4) << 4));

    for (int kg = kg0; kg < kg0 + kchunk; kg += 32) {
        // ---- stage A tile (32x32 bf16, hi+lo) ----
        *(uint4*)(sm + adst) = *(const uint4*)(Asrc + kg + achk * 8);
        // ---- stage B tile = W[kg..kg+32)[n0..n0+256), convert to bf16 hi/lo ----
        const float* Wp = W + (size_t)kg * Nout + n0;
#pragma unroll
        for (int r = 0; r < 8; r++) {
            const int idx = tid + r * 256;
            const int k = idx >> 6, c4 = idx & 63;
            const float4 wv = *(const float4*)(Wp + (size_t)k * Nout + c4 * 4);
            const uint32_t h01 = cvt2_bf16(wv.x, wv.y);
            const uint32_t h23 = cvt2_bf16(wv.z, wv.w);
            const float l0 = wv.x - __uint_as_float(h01 << 16);
            const float l1 = wv.y - __uint_as_float(h01 & 0xffff0000u);
            const float l2 = wv.z - __uint_as_float(h23 << 16);
            const float l3 = wv.w - __uint_as_float(h23 & 0xffff0000u);
            const uint32_t l01 = cvt2_bf16(l0, l1);
            const uint32_t l23 = cvt2_bf16(l2, l3);
            const int d = k * 528 + c4 * 8;
            *(uint2*)(sm + SMB_H + d) = make_uint2(h01, h23);
            *(uint2*)(sm + SMB_L + d) = make_uint2(l01, l23);
        }
        __syncthreads();
        // ---- compute: 2 k16-halves ----
#pragma unroll
        for (int kh = 0; kh < 2; kh++) {
            uint32_t ah0[4], ah1[4], al0[4], al1[4];
            ldmA(ah0, sb + SMA_H + aoff + kh * 32);
            ldmA(ah1, sb + SMA_H + aoff + kh * 32 + 1280);
            ldmA(al0, sb + SMA_L + aoff + kh * 32);
            ldmA(al1, sb + SMA_L + aoff + kh * 32 + 1280);
            uint32_t bh[8], bl[8];
            ldmB(bh + 0, sb + SMB_H + boff + kh * 8448);
            ldmB(bh + 4, sb + SMB_H + boff + kh * 8448 + 32);
            ldmB(bl + 0, sb + SMB_L + boff + kh * 8448);
            ldmB(bl + 4, sb + SMB_L + boff + kh * 8448 + 32);
#pragma unroll
            for (int nt = 0; nt < 4; nt++) {
                const uint32_t* bhn = &bh[nt * 2];
                const uint32_t* bln = &bl[nt * 2];
                mma_bf16(acc[0][nt], ah0, bhn);
                mma_bf16(acc[0][nt], ah0, bln);
                mma_bf16(acc[0][nt], al0, bhn);
                mma_bf16(acc[1][nt], ah1, bhn);
                mma_bf16(acc[1][nt], ah1, bln);
                mma_bf16(acc[1][nt], al1, bhn);
            }
        }
        __syncthreads();
    }
    // ---- write partials ----
#pragma unroll
    for (int mt = 0; mt < 2; mt++)
#pragma unroll
        for (int nt = 0; nt < 4; nt++) {
            const int m = mt * 16 + (lane >> 2);
            const int n = n0 + wp * 32 + nt * 8 + (lane & 3) * 2;
            float* base = &g_part[((size_t)blockIdx.y * 32 + m) * Nout + n];
            *(float2*)base = make_float2(acc[mt][nt][0], acc[mt][nt][1]);
            *(float2*)(base + (size_t)8 * Nout) = make_float2(acc[mt][nt][2], acc[mt][nt][3]);
        }
}

// ---------------- LayerNorm -> bf16 hi/lo activations ----------------
__global__ __launch_bounds__(256) void ln_kernel(const float* __restrict__ x_ext,
                                                 int use_x1, int row0,
                                                 const float* __restrict__ sc,
                                                 const float* __restrict__ bi) {
    const float* x = use_x1 ? g_x1 : x_ext;
    const int b = blockIdx.x + row0, tid = threadIdx.x;
    const int warp = tid >> 5, lane = tid & 31;
    const float* xr = x + b * CC;
    float v[8];
    float s = 0.f;
#pragma unroll
    for (int i = 0; i < 8; i++) { v[i] = xr[tid + i * 256]; s += v[i]; }
    __shared__ float red[8];
#pragma unroll
    for (int o = 16; o > 0; o >>= 1) s += __shfl_xor_sync(0xffffffffu, s, o);
    if (lane == 0) red[warp] = s;
    __syncthreads();
    s = red[0];
#pragma unroll
    for (int i = 1; i < 8; i++) s += red[i];
    const float mean = s * (1.f / (float)CC);
    float q = 0.f;
#pragma unroll
    for (int i = 0; i < 8; i++) { float d = v[i] - mean; q += d * d; }
    __syncthreads();
#pragma unroll
    for (int o = 16; o > 0; o >>= 1) q += __shfl_xor_sync(0xffffffffu, q, o);
    if (lane == 0) red[warp] = q;
    __syncthreads();
    q = red[0];
#pragma unroll
    for (int i = 1; i < 8; i++) q += red[i];
    const float r = rsqrtf(q * (1.f / (float)CC) + 1e-5f);
#pragma unroll
    for (int i = 0; i < 8; i++) {
        const int n = tid + i * 256;
        const float val = (v[i] - mean) * r * sc[n] + bi[n];
        const __nv_bfloat16 hb = __float2bfloat16_rn(val);
        g_ah[b * CC + n] = hb;
        g_al[b * CC + n] = __float2bfloat16_rn(val - __bfloat162float(hb));
    }
}

// ---------------- reduce: qkv (bias + scatter q/k/v), 16 chunks ----------------
__global__ __launch_bounds__(256) void red_qkv(const float* __restrict__ bias,
                                               float* __restrict__ ok,
                                               float* __restrict__ ov) {
    const int i4 = blockIdx.x * 256 + threadIdx.x;   // < 49152
    const int row = i4 / 1536, n4 = i4 % 1536;
    const float4* p = ((const float4*)g_part) + i4;
    float4 s0 = make_float4(0, 0, 0, 0), s1 = s0;
#pragma unroll
    for (int c = 0; c < 16; c += 2) {
        const float4 a = p[(size_t)c * 49152];
        const float4 b = p[(size_t)(c + 1) * 49152];
        s0.x += a.x; s0.y += a.y; s0.z += a.z; s0.w += a.w;
        s1.x += b.x; s1.y += b.y; s1.z += b.z; s1.w += b.w;
    }
    const float4 bi = ((const float4*)bias)[n4];
    float4 s = make_float4(s0.x + s1.x + bi.x, s0.y + s1.y + bi.y,
                           s0.z + s1.z + bi.z, s0.w + s1.w + bi.w);
    if (n4 < 512)       ((float4*)g_q)[row * 512 + n4] = s;
    else if (n4 < 1024) ((float4*)ok)[row * 512 + n4 - 512] = s;
    else                ((float4*)ov)[row * 512 + n4 - 1024] = s;
}

// ---------------- reduce: bias + residual -> fp32 (proj & mlp) ----------------
__global__ __launch_bounds__(256) void red_resid(const float* __restrict__ bias,
                                                 const float* __restrict__ resid_ext,
                                                 int resid_x1,
                                                 float* __restrict__ dst_ext,
                                                 int dst_x1, int nchunk) {
    const float* resid = resid_x1 ? g_x1 : resid_ext;
    float* dst = dst_x1 ? g_x1 : dst_ext;
    const int i4 = blockIdx.x * 256 + threadIdx.x;   // < 16384 (N=2048)
    const int n4 = i4 & 511;
    const float4* p = ((const float4*)g_part) + i4;
    float4 s0 = make_float4(0, 0, 0, 0), s1 = s0, s2 = s0, s3 = s0;
    for (int c = 0; c < nchunk; c += 4) {
        const float4 a = p[(size_t)c * 16384];
        const float4 b = p[(size_t)(c + 1) * 16384];
        const float4 cc = p[(size_t)(c + 2) * 16384];
        const float4 d = p[(size_t)(c + 3) * 16384];
        s0.x += a.x; s0.y += a.y; s0.z += a.z; s0.w += a.w;
        s1.x += b.x; s1.y += b.y; s1.z += b.z; s1.w += b.w;
        s2.x += cc.x; s2.y += cc.y; s2.z += cc.z; s2.w += cc.w;
        s3.x += d.x; s3.y += d.y; s3.z += d.z; s3.w += d.w;
    }
    const float4 bi = ((const float4*)bias)[n4];
    const float4 r = ((const float4*)resid)[i4];
    float4 s = make_float4(s0.x + s1.x + s2.x + s3.x + bi.x + r.x,
                           s0.y + s1.y + s2.y + s3.y + bi.y + r.y,
                           s0.z + s1.z + s2.z + s3.z + bi.z + r.z,
                           s0.w + s1.w + s2.w + s3.w + bi.w + r.w);
    ((float4*)dst)[i4] = s;
}

// ---------------- reduce: bias + gelu -> bf16 hi/lo (fc), 8 chunks ----------------
__global__ __launch_bounds__(256) void red_gelu(const float* __restrict__ bias) {
    const int i4 = blockIdx.x * 256 + threadIdx.x;   // < 65536 (N=8192)
    const int n4 = i4 & 2047;
    const float4* p = ((const float4*)g_part) + i4;
    float4 s0 = make_float4(0, 0, 0, 0), s1 = s0;
#pragma unroll
    for (int c = 0; c < 8; c += 2) {
        const float4 a = p[(size_t)c * 65536];
        const float4 b = p[(size_t)(c + 1) * 65536];
        s0.x += a.x; s0.y += a.y; s0.z += a.z; s0.w += a.w;
        s1.x += b.x; s1.y += b.y; s1.z += b.z; s1.w += b.w;
    }
    const float4 bi = ((const float4*)bias)[n4];
    const float g0 = gelu1(s0.x + s1.x + bi.x), g1 = gelu1(s0.y + s1.y + bi.y);
    const float g2 = gelu1(s0.z + s1.z + bi.z), g3 = gelu1(s0.w + s1.w + bi.w);
    const uint32_t h01 = cvt2_bf16(g0, g1), h23 = cvt2_bf16(g2, g3);
    const float l0 = g0 - __uint_as_float(h01 << 16);
    const float l1 = g1 - __uint_as_float(h01 & 0xffff0000u);
    const float l2 = g2 - __uint_as_float(h23 << 16);
    const float l3 = g3 - __uint_as_float(h23 & 0xffff0000u);
    ((uint2*)g_ah)[i4] = make_uint2(h01, h23);
    ((uint2*)g_al)[i4] = make_uint2(cvt2_bf16(l0, l1), cvt2_bf16(l2, l3));
}

// ---------------- flash-decode attention (90us @ 77% spec, unchanged) ----------------
__global__ __launch_bounds__(128) void attn_partial(const float* __restrict__ Kc,
                                                    const float* __restrict__ Vc,
                                                    const int* __restrict__ pos) {
    const int c = blockIdx.x, h = blockIdx.y, b = blockIdx.z;
    const int p = pos[b];
    const int tbase = c * TCH;
    if (tbase > p) return;
    const int tcnt = min(TCH, p + 1 - tbase);
    __shared__ float s[TCH];
    __shared__ float red[4];
    const int tid = threadIdx.x, warp = tid >> 5, lane = tid & 31;
    const int sub = lane >> 3, d8 = lane & 7;

    float4 qa[4];
    {
        const float* qp = &g_q[b * CC + h * HD + d8 * 16];
#pragma unroll
        for (int j = 0; j < 4; j++) {
            qa[j] = *(const float4*)&qp[j * 4];
            qa[j].x *= ATT_SCALE; qa[j].y *= ATT_SCALE;
            qa[j].z *= ATT_SCALE; qa[j].w *= ATT_SCALE;
        }
    }
#pragma unroll
    for (int it = 0; it < 8; it++) {
        const int t = warp * 32 + it * 4 + sub;
        float d = 0.f;
        if (t < tcnt) {
            const float* kp =
                &Kc[((size_t)((b * TT + tbase + t) * HH + h)) * HD + d8 * 16];
#pragma unroll
            for (int j = 0; j < 4; j++) {
                const float4 kv = *(const float4*)&kp[j * 4];
                d += qa[j].x * kv.x + qa[j].y * kv.y + qa[j].z * kv.z + qa[j].w * kv.w;
            }
        }
        d += __shfl_xor_sync(0xffffffffu, d, 4);
        d += __shfl_xor_sync(0xffffffffu, d, 2);
        d += __shfl_xor_sync(0xffffffffu, d, 1);
        if (d8 == 0 && t < tcnt) s[t] = d;
    }
    __syncthreads();

    const float sv = (tid < tcnt) ? s[tid] : -3.4e38f;
    float mx = sv;
#pragma unroll
    for (int o = 16; o > 0; o >>= 1) mx = fmaxf(mx, __shfl_xor_sync(0xffffffffu, mx, o));
    if (lane == 0) red[warp] = mx;
    __syncthreads();
    mx = fmaxf(fmaxf(red[0], red[1]), fmaxf(red[2], red[3]));
    const float e = (tid < tcnt) ? __expf(sv - mx) : 0.f;
    __syncthreads();
    s[tid] = e;
    float sum = e;
#pragma unroll
    for (int o = 16; o > 0; o >>= 1) sum += __shfl_xor_sync(0xffffffffu, sum, o);
    if (lane == 0) red[warp] = sum;
    __syncthreads();
    sum = red[0] + red[1] + red[2] + red[3];

    float acc = 0.f;
    const float* vp = &Vc[((size_t)((b * TT + tbase) * HH + h)) * HD + tid];
    const int t_end = (tcnt + 7) & ~7;
    for (int t = 0; t < t_end; t += 8) {
        float v0 = vp[(size_t)(t + 0) * CC];
        float v1 = vp[(size_t)(t + 1) * CC];
        float v2 = vp[(size_t)(t + 2) * CC];
        float v3 = vp[(size_t)(t + 3) * CC];
        float v4 = vp[(size_t)(t + 4) * CC];
        float v5 = vp[(size_t)(t + 5) * CC];
        float v6 = vp[(size_t)(t + 6) * CC];
        float v7 = vp[(size_t)(t + 7) * CC];
        acc += s[t] * v0 + s[t + 1] * v1 + s[t + 2] * v2 + s[t + 3] * v3;
        acc += s[t + 4] * v4 + s[t + 5] * v5 + s[t + 6] * v6 + s[t + 7] * v7;
    }
    const int idx = (b * HH + h) * NCH + c;
    g_po[idx * HD + tid] = acc;
    if (tid == 0) { g_pm[idx] = mx; g_pl[idx] = sum; }
}

// combine -> bf16 hi/lo activations (input of proj GEMM)
__global__ __launch_bounds__(128) void attn_combine(const int* __restrict__ pos) {
    const int bh = blockIdx.x;
    const int b = bh >> 4, h = bh & 15;
    const int nch = (pos[b] >> 7) + 1;
    const int tid = threadIdx.x;
    float gm = -3.4e38f;
    for (int c = 0; c < nch; c++) gm = fmaxf(gm, g_pm[bh * NCH + c]);
    float l = 0.f, acc = 0.f;
    for (int c = 0; c < nch; c++) {
        const float w = __expf(g_pm[bh * NCH + c] - gm);
        l += g_pl[bh * NCH + c] * w;
        acc += g_po[(bh * NCH + c) * HD + tid] * w;
    }
    const float val = acc / l;
    const int di = b * CC + h * HD + tid;
    const __nv_bfloat16 hb = __float2bfloat16_rn(val);
    g_ah[di] = hb;
    g_al[di] = __float2bfloat16_rn(val - __bfloat162float(hb));
}

// ---------------- launch: kernel launches ONLY ----------------
extern "C" void kernel_launch(void* const* d_in, const int* in_sizes, int n_in,
                              void* d_out, int out_size) {
    const float* x           = (const float*)d_in[0];
    const float* prev_k      = (const float*)d_in[1];
    const float* prev_v      = (const float*)d_in[2];
    const int*   pos         = (const int*)d_in[3];
    const float* ln1_scale   = (const float*)d_in[4];
    const float* ln1_bias    = (const float*)d_in[5];
    const float* w_attn      = (const float*)d_in[6];
    const float* b_attn      = (const float*)d_in[7];
    const float* w_attn_proj = (const float*)d_in[8];
    const float* b_attn_proj = (const float*)d_in[9];
    const float* ln2_scale   = (const float*)d_in[10];
    const float* ln2_bias    = (const float*)d_in[11];
    const float* w_fc        = (const float*)d_in[12];
    const float* b_fc        = (const float*)d_in[13];
    const float* w_mlp_proj  = (const float*)d_in[14];
    const float* b_mlp_proj  = (const float*)d_in[15];
    float* out = (float*)d_out;   // [x | k_new | v_new]

    // 0-2. LN1 in 3 launches (puts gemm_tc(qkv) at launch idx 3 for ncu)
    ln_kernel<<<11, 256>>>(x, 0, 0, ln1_scale, ln1_bias);
    ln_kernel<<<11, 256>>>(x, 0, 11, ln1_scale, ln1_bias);
    ln_kernel<<<10, 256>>>(x, 0, 22, ln1_scale, ln1_bias);
    // 3. qkv GEMM: K=2048, N=6144; 24 n-blocks x 16 k-chunks(128) = 384 blocks
    gemm_tc<<<dim3(24, 16), 256, SM_GEMM>>>(w_attn, 2048, 6144, 128);
    // 4. reduce qkv: bias + scatter q / k_new / v_new (16 chunks)
    red_qkv<<<192, 256>>>(b_attn, out + 65536, out + 131072);
    // 5-6. attention
    attn_partial<<<dim3(NCH, HH, BB), 128>>>(prev_k, prev_v, pos);
    attn_combine<<<BB * HH, 128>>>(pos);
    // 7. attn proj GEMM: K=2048, N=2048; 8 x 32 k-chunks(64) = 256 blocks
    gemm_tc<<<dim3(8, 32), 256, SM_GEMM>>>(w_attn_proj, 2048, 2048, 64);
    // 8. reduce: bias + resid(x) -> g_x1 (32 chunks)
    red_resid<<<64, 256>>>(b_attn_proj, x, 0, nullptr, 1, 32);
    // 9. LN2: g_x1 -> hi/lo
    ln_kernel<<<32, 256>>>(nullptr, 1, 0, ln2_scale, ln2_bias);
    // 10. fc GEMM: K=2048, N=8192; 32 x 8 k-chunks(256) = 256 blocks
    gemm_tc<<<dim3(32, 8), 256, SM_GEMM>>>(w_fc, 2048, 8192, 256);
    // 11. reduce: bias + gelu -> hi/lo (8 chunks)
    red_gelu<<<256, 256>>>(b_fc);
    // 12. mlp proj GEMM: K=8192, N=2048; 8 x 64 k-chunks(128) = 512 blocks
    gemm_tc<<<dim3(8, 64), 256, SM_GEMM>>>(w_mlp_proj, 8192, 2048, 128);
    // 13. reduce: bias + resid(g_x1) -> out (64 chunks)
    red_resid<<<64, 256>>>(b_mlp_proj, nullptr, 1, out, 0, 64);
}

// round 10
// speedup vs baseline: 1.6252x; 1.0272x over previous
#include <cuda_runtime.h>
#include <cuda_bf16.h>
#include <math.h>
#include <stdint.h>

// Problem dims
#define BB 32
#define TT 2048
#define HH 16
#define HD 128
#define CC 2048
#define TCH 128
#define NCH 16
#define ATT_SCALE 0.08838834764831845f

// ---------------- scratch (device globals) ----------------
__device__ float g_q[BB * CC];                 // q (fp32, for attention)
__device__ float g_x1[BB * CC];                // x + attn_proj (fp32)
__device__ float g_part[4194304];              // split-K partials (max 64*32*2048)
__device__ __nv_bfloat16 g_ah[BB * 8192];      // activation hi (GEMM A side)
__device__ __nv_bfloat16 g_al[BB * 8192];      // activation lo
__device__ float g_pm[BB * HH * NCH];
__device__ float g_pl[BB * HH * NCH];
__device__ float g_po[BB * HH * NCH * HD];

// ---------------- helpers ----------------
__device__ __forceinline__ uint32_t smem_u32(const void* p) {
    return (uint32_t)__cvta_generic_to_shared(p);
}
// pack two floats as bf16x2: low half = lo, high half = hi
__device__ __forceinline__ uint32_t cvt2_bf16(float lo, float hi) {
    uint32_t r;
    asm("cvt.rn.bf16x2.f32 %0, %1, %2;" : "=r"(r) : "f"(hi), "f"(lo));
    return r;
}
__device__ __forceinline__ void ldmA(uint32_t* r, uint32_t addr) {
    asm volatile("ldmatrix.sync.aligned.m8n8.x4.shared.b16 {%0,%1,%2,%3}, [%4];"
                 : "=r"(r[0]), "=r"(r[1]), "=r"(r[2]), "=r"(r[3]) : "r"(addr));
}
__device__ __forceinline__ void ldmB(uint32_t* r, uint32_t addr) {
    asm volatile("ldmatrix.sync.aligned.m8n8.x4.trans.shared.b16 {%0,%1,%2,%3}, [%4];"
                 : "=r"(r[0]), "=r"(r[1]), "=r"(r[2]), "=r"(r[3]) : "r"(addr));
}
__device__ __forceinline__ void mma_bf16(float* c, const uint32_t* a, const uint32_t* b) {
    asm volatile(
        "mma.sync.aligned.m16n8k16.row.col.f32.bf16.bf16.f32 "
        "{%0,%1,%2,%3}, {%4,%5,%6,%7}, {%8,%9}, {%0,%1,%2,%3};"
        : "+f"(c[0]), "+f"(c[1]), "+f"(c[2]), "+f"(c[3])
        : "r"(a[0]), "r"(a[1]), "r"(a[2]), "r"(a[3]), "r"(b[0]), "r"(b[1]));
}
__device__ __forceinline__ float gelu1(float s) {
    const float x3 = s * s * s;
    return 0.5f * s * (1.f + tanhf(0.7978845608028654f * (s + 0.044715f * x3)));
}

// ---- SMEM layout for pipelined gemm_tc (bytes) ----
// Strides MUST be multiples of 16 (uint4 STS + ldmatrix row alignment).
// A group (32-k) buffers: 32 rows x 80B (64 data + 16 pad; conflict-free 16-row ldm)
#define A_STRIDE 80
#define A_BUF 2560                       // 32*80
#define SMA(buf, hl) ((buf) * (2 * A_BUF) + (hl) * A_BUF)          // [0, 10240)
// B half (16-k) buffers: 16 rows x 528B (512 data + 16 pad)
#define B_STRIDE 528
#define B_BUF 8448                       // 16*528
#define SMB(buf, hl) (10240 + (buf) * (2 * B_BUF) + (hl) * B_BUF)  // [10240, 44032)
#define SM_GEMM 44032

// ============ pipelined tensor-core GEMM partial ============
// Block tile: 32 batch rows x 256 W cols; K in 16-row halves, register-prefetched
// W (4xLDG.128/thread) one half ahead; bf16 hi/lo B double-buffered in SMEM; A
// (pre-split bf16 in global) double-buffered per 32-k group with 1-iter prefetch.
// One __syncthreads per 16-k half. 3-term split: Ah*Bh + Ah*Bl + Al*Bh.
__global__ __launch_bounds__(256, 2) void gemm_tc(const float* __restrict__ W,
                                                  int Ktot, int Nout, int kchunk) {
    extern __shared__ unsigned char sm[];
    const uint32_t sb = smem_u32(sm);
    const int tid = threadIdx.x, lane = tid & 31, wp = tid >> 5;
    const int n0 = blockIdx.x * 256;
    const int kg0 = blockIdx.y * kchunk;
    const int H = kchunk >> 4;          // 16-k halves
    const int G = H >> 1;               // 32-k A groups

    float acc[2][4][4];
#pragma unroll
    for (int mt = 0; mt < 2; mt++)
#pragma unroll
        for (int nt = 0; nt < 4; nt++)
#pragma unroll
            for (int i = 0; i < 4; i++) acc[mt][nt][i] = 0.f;

    // B load/stage coords: float4 id = tid + r*256 -> row=(id>>6), col=(id&63)
    const int brow = tid >> 6;          // base row 0..3 (actual row = brow + r*4)
    const int bcol = tid & 63;
    // A stage coords: threads 0-127 stage hi, 128-255 stage lo; 16B each
    const int ar = tid & 127;
    const int arow = ar >> 2, achk = ar & 3;
    const int ahl = tid >> 7;
    const __nv_bfloat16* Asrc = (ahl ? g_al : g_ah) + (size_t)arow * Ktot;
    const int adst = arow * A_STRIDE + achk * 16;

    // ldmatrix fragment base offsets
    const uint32_t aoff = (uint32_t)((lane & 15) * A_STRIDE + ((lane >> 4) << 4));
    const uint32_t boff = (uint32_t)((lane & 15) * B_STRIDE + wp * 64 + ((lane >> 4) << 4));

    // preload: B half 0 and A group 0
    float4 rb[4];
#pragma unroll
    for (int r = 0; r < 4; r++)
        rb[r] = *(const float4*)(W + (size_t)(kg0 + brow + r * 4) * Nout + n0 + bcol * 4);
    uint4 ra = *(const uint4*)(Asrc + kg0 + achk * 8);

    for (int h = 0; h < H; h++) {
        const int g = h >> 1;
        const int bbuf = h & 1, abuf = g & 1, kh = h & 1;
        // A: stage current group on even halves; prefetch next group on odd halves
        if (kh == 0) {
            *(uint4*)(sm + SMA(abuf, ahl) + adst) = ra;
        } else if (g + 1 < G) {
            ra = *(const uint4*)(Asrc + kg0 + (g + 1) * 32 + achk * 8);
        }
        // convert prefetched B regs -> bf16 hi/lo SMEM buffer bbuf
#pragma unroll
        for (int r = 0; r < 4; r++) {
            const float4 wv = rb[r];
            const uint32_t h01 = cvt2_bf16(wv.x, wv.y);
            const uint32_t h23 = cvt2_bf16(wv.z, wv.w);
            const float l0 = wv.x - __uint_as_float(h01 << 16);
            const float l1 = wv.y - __uint_as_float(h01 & 0xffff0000u);
            const float l2 = wv.z - __uint_as_float(h23 << 16);
            const float l3 = wv.w - __uint_as_float(h23 & 0xffff0000u);
            const int d = (brow + r * 4) * B_STRIDE + bcol * 8;
            *(uint2*)(sm + SMB(bbuf, 0) + d) = make_uint2(h01, h23);
            *(uint2*)(sm + SMB(bbuf, 1) + d) = make_uint2(cvt2_bf16(l0, l1), cvt2_bf16(l2, l3));
        }
        // prefetch next B half (latency hidden under compute below)
        if (h + 1 < H) {
            const int kb = kg0 + (h + 1) * 16;
#pragma unroll
            for (int r = 0; r < 4; r++)
                rb[r] = *(const float4*)(W + (size_t)(kb + brow + r * 4) * Nout + n0 + bcol * 4);
        }
        __syncthreads();
        // compute this k16 half
        uint32_t ah0[4], ah1[4], al0[4], al1[4];
        ldmA(ah0, sb + SMA(abuf, 0) + aoff + kh * 32);
        ldmA(ah1, sb + SMA(abuf, 0) + aoff + kh * 32 + 16 * A_STRIDE);
        ldmA(al0, sb + SMA(abuf, 1) + aoff + kh * 32);
        ldmA(al1, sb + SMA(abuf, 1) + aoff + kh * 32 + 16 * A_STRIDE);
        uint32_t bh[8], bl[8];
        ldmB(bh + 0, sb + SMB(bbuf, 0) + boff);
        ldmB(bh + 4, sb + SMB(bbuf, 0) + boff + 32);
        ldmB(bl + 0, sb + SMB(bbuf, 1) + boff);
        ldmB(bl + 4, sb + SMB(bbuf, 1) + boff + 32);
#pragma unroll
        for (int nt = 0; nt < 4; nt++) {
            const uint32_t* bhn = &bh[nt * 2];
            const uint32_t* bln = &bl[nt * 2];
            mma_bf16(acc[0][nt], ah0, bhn);
            mma_bf16(acc[0][nt], ah0, bln);
            mma_bf16(acc[0][nt], al0, bhn);
            mma_bf16(acc[1][nt], ah1, bhn);
            mma_bf16(acc[1][nt], ah1, bln);
            mma_bf16(acc[1][nt], al1, bhn);
        }
        // no trailing sync: next iteration writes the OTHER buffers; sync(h+1)
        // orders compute(h) readers before stage(h+2) writers.
    }
    // ---- write partials ----
#pragma unroll
    for (int mt = 0; mt < 2; mt++)
#pragma unroll
        for (int nt = 0; nt < 4; nt++) {
            const int m = mt * 16 + (lane >> 2);
            const int n = n0 + wp * 32 + nt * 8 + (lane & 3) * 2;
            float* base = &g_part[((size_t)blockIdx.y * 32 + m) * Nout + n];
            *(float2*)base = make_float2(acc[mt][nt][0], acc[mt][nt][1]);
            *(float2*)(base + (size_t)8 * Nout) = make_float2(acc[mt][nt][2], acc[mt][nt][3]);
        }
}

// ---------------- LayerNorm -> bf16 hi/lo activations ----------------
__global__ __launch_bounds__(256) void ln_kernel(const float* __restrict__ x_ext,
                                                 int use_x1, int row0,
                                                 const float* __restrict__ sc,
                                                 const float* __restrict__ bi) {
    const float* x = use_x1 ? g_x1 : x_ext;
    const int b = blockIdx.x + row0, tid = threadIdx.x;
    const int warp = tid >> 5, lane = tid & 31;
    const float* xr = x + b * CC;
    float v[8];
    float s = 0.f;
#pragma unroll
    for (int i = 0; i < 8; i++) { v[i] = xr[tid + i * 256]; s += v[i]; }
    __shared__ float red[8];
#pragma unroll
    for (int o = 16; o > 0; o >>= 1) s += __shfl_xor_sync(0xffffffffu, s, o);
    if (lane == 0) red[warp] = s;
    __syncthreads();
    s = red[0];
#pragma unroll
    for (int i = 1; i < 8; i++) s += red[i];
    const float mean = s * (1.f / (float)CC);
    float q = 0.f;
#pragma unroll
    for (int i = 0; i < 8; i++) { float d = v[i] - mean; q += d * d; }
    __syncthreads();
#pragma unroll
    for (int o = 16; o > 0; o >>= 1) q += __shfl_xor_sync(0xffffffffu, q, o);
    if (lane == 0) red[warp] = q;
    __syncthreads();
    q = red[0];
#pragma unroll
    for (int i = 1; i < 8; i++) q += red[i];
    const float r = rsqrtf(q * (1.f / (float)CC) + 1e-5f);
#pragma unroll
    for (int i = 0; i < 8; i++) {
        const int n = tid + i * 256;
        const float val = (v[i] - mean) * r * sc[n] + bi[n];
        const __nv_bfloat16 hb = __float2bfloat16_rn(val);
        g_ah[b * CC + n] = hb;
        g_al[b * CC + n] = __float2bfloat16_rn(val - __bfloat162float(hb));
    }
}

// ---------------- reduce: qkv (bias + scatter q/k/v), 16 chunks ----------------
__global__ __launch_bounds__(256) void red_qkv(const float* __restrict__ bias,
                                               float* __restrict__ ok,
                                               float* __restrict__ ov) {
    const int i4 = blockIdx.x * 256 + threadIdx.x;   // < 49152
    const int row = i4 / 1536, n4 = i4 % 1536;
    const float4* p = ((const float4*)g_part) + i4;
    float4 s0 = make_float4(0, 0, 0, 0), s1 = s0;
#pragma unroll
    for (int c = 0; c < 16; c += 2) {
        const float4 a = p[(size_t)c * 49152];
        const float4 b = p[(size_t)(c + 1) * 49152];
        s0.x += a.x; s0.y += a.y; s0.z += a.z; s0.w += a.w;
        s1.x += b.x; s1.y += b.y; s1.z += b.z; s1.w += b.w;
    }
    const float4 bi = ((const float4*)bias)[n4];
    float4 s = make_float4(s0.x + s1.x + bi.x, s0.y + s1.y + bi.y,
                           s0.z + s1.z + bi.z, s0.w + s1.w + bi.w);
    if (n4 < 512)       ((float4*)g_q)[row * 512 + n4] = s;
    else if (n4 < 1024) ((float4*)ok)[row * 512 + n4 - 512] = s;
    else                ((float4*)ov)[row * 512 + n4 - 1024] = s;
}

// ---------------- reduce: bias + residual -> fp32 (proj & mlp) ----------------
__global__ __launch_bounds__(256) void red_resid(const float* __restrict__ bias,
                                                 const float* __restrict__ resid_ext,
                                                 int resid_x1,
                                                 float* __restrict__ dst_ext,
                                                 int dst_x1, int nchunk) {
    const float* resid = resid_x1 ? g_x1 : resid_ext;
    float* dst = dst_x1 ? g_x1 : dst_ext;
    const int i4 = blockIdx.x * 256 + threadIdx.x;   // < 16384 (N=2048)
    const int n4 = i4 & 511;
    const float4* p = ((const float4*)g_part) + i4;
    float4 s0 = make_float4(0, 0, 0, 0), s1 = s0, s2 = s0, s3 = s0;
    for (int c = 0; c < nchunk; c += 4) {
        const float4 a = p[(size_t)c * 16384];
        const float4 b = p[(size_t)(c + 1) * 16384];
        const float4 cc = p[(size_t)(c + 2) * 16384];
        const float4 d = p[(size_t)(c + 3) * 16384];
        s0.x += a.x; s0.y += a.y; s0.z += a.z; s0.w += a.w;
        s1.x += b.x; s1.y += b.y; s1.z += b.z; s1.w += b.w;
        s2.x += cc.x; s2.y += cc.y; s2.z += cc.z; s2.w += cc.w;
        s3.x += d.x; s3.y += d.y; s3.z += d.z; s3.w += d.w;
    }
    const float4 bi = ((const float4*)bias)[n4];
    const float4 r = ((const float4*)resid)[i4];
    float4 s = make_float4(s0.x + s1.x + s2.x + s3.x + bi.x + r.x,
                           s0.y + s1.y + s2.y + s3.y + bi.y + r.y,
                           s0.z + s1.z + s2.z + s3.z + bi.z + r.z,
                           s0.w + s1.w + s2.w + s3.w + bi.w + r.w);
    ((float4*)dst)[i4] = s;
}

// ---------------- reduce: bias + gelu -> bf16 hi/lo (fc), 16 chunks ----------------
__global__ __launch_bounds__(256) void red_gelu(const float* __restrict__ bias) {
    const int i4 = blockIdx.x * 256 + threadIdx.x;   // < 65536 (N=8192)
    const int n4 = i4 & 2047;
    const float4* p = ((const float4*)g_part) + i4;
    float4 s0 = make_float4(0, 0, 0, 0), s1 = s0;
#pragma unroll
    for (int c = 0; c < 16; c += 2) {
        const float4 a = p[(size_t)c * 65536];
        const float4 b = p[(size_t)(c + 1) * 65536];
        s0.x += a.x; s0.y += a.y; s0.z += a.z; s0.w += a.w;
        s1.x += b.x; s1.y += b.y; s1.z += b.z; s1.w += b.w;
    }
    const float4 bi = ((const float4*)bias)[n4];
    const float g0 = gelu1(s0.x + s1.x + bi.x), g1 = gelu1(s0.y + s1.y + bi.y);
    const float g2 = gelu1(s0.z + s1.z + bi.z), g3 = gelu1(s0.w + s1.w + bi.w);
    const uint32_t h01 = cvt2_bf16(g0, g1), h23 = cvt2_bf16(g2, g3);
    const float l0 = g0 - __uint_as_float(h01 << 16);
    const float l1 = g1 - __uint_as_float(h01 & 0xffff0000u);
    const float l2 = g2 - __uint_as_float(h23 << 16);
    const float l3 = g3 - __uint_as_float(h23 & 0xffff0000u);
    ((uint2*)g_ah)[i4] = make_uint2(h01, h23);
    ((uint2*)g_al)[i4] = make_uint2(cvt2_bf16(l0, l1), cvt2_bf16(l2, l3));
}

// ---------------- flash-decode attention (90us @ 77% spec, unchanged) ----------------
__global__ __launch_bounds__(128) void attn_partial(const float* __restrict__ Kc,
                                                    const float* __restrict__ Vc,
                                                    const int* __restrict__ pos) {
    const int c = blockIdx.x, h = blockIdx.y, b = blockIdx.z;
    const int p = pos[b];
    const int tbase = c * TCH;
    if (tbase > p) return;
    const int tcnt = min(TCH, p + 1 - tbase);
    __shared__ float s[TCH];
    __shared__ float red[4];
    const int tid = threadIdx.x, warp = tid >> 5, lane = tid & 31;
    const int sub = lane >> 3, d8 = lane & 7;

    float4 qa[4];
    {
        const float* qp = &g_q[b * CC + h * HD + d8 * 16];
#pragma unroll
        for (int j = 0; j < 4; j++) {
            qa[j] = *(const float4*)&qp[j * 4];
            qa[j].x *= ATT_SCALE; qa[j].y *= ATT_SCALE;
            qa[j].z *= ATT_SCALE; qa[j].w *= ATT_SCALE;
        }
    }
#pragma unroll
    for (int it = 0; it < 8; it++) {
        const int t = warp * 32 + it * 4 + sub;
        float d = 0.f;
        if (t < tcnt) {
            const float* kp =
                &Kc[((size_t)((b * TT + tbase + t) * HH + h)) * HD + d8 * 16];
#pragma unroll
            for (int j = 0; j < 4; j++) {
                const float4 kv = *(const float4*)&kp[j * 4];
                d += qa[j].x * kv.x + qa[j].y * kv.y + qa[j].z * kv.z + qa[j].w * kv.w;
            }
        }
        d += __shfl_xor_sync(0xffffffffu, d, 4);
        d += __shfl_xor_sync(0xffffffffu, d, 2);
        d += __shfl_xor_sync(0xffffffffu, d, 1);
        if (d8 == 0 && t < tcnt) s[t] = d;
    }
    __syncthreads();

    const float sv = (tid < tcnt) ? s[tid] : -3.4e38f;
    float mx = sv;
#pragma unroll
    for (int o = 16; o > 0; o >>= 1) mx = fmaxf(mx, __shfl_xor_sync(0xffffffffu, mx, o));
    if (lane == 0) red[warp] = mx;
    __syncthreads();
    mx = fmaxf(fmaxf(red[0], red[1]), fmaxf(red[2], red[3]));
    const float e = (tid < tcnt) ? __expf(sv - mx) : 0.f;
    __syncthreads();
    s[tid] = e;
    float sum = e;
#pragma unroll
    for (int o = 16; o > 0; o >>= 1) sum += __shfl_xor_sync(0xffffffffu, sum, o);
    if (lane == 0) red[warp] = sum;
    __syncthreads();
    sum = red[0] + red[1] + red[2] + red[3];

    float acc = 0.f;
    const float* vp = &Vc[((size_t)((b * TT + tbase) * HH + h)) * HD + tid];
    const int t_end = (tcnt + 7) & ~7;
    for (int t = 0; t < t_end; t += 8) {
        float v0 = vp[(size_t)(t + 0) * CC];
        float v1 = vp[(size_t)(t + 1) * CC];
        float v2 = vp[(size_t)(t + 2) * CC];
        float v3 = vp[(size_t)(t + 3) * CC];
        float v4 = vp[(size_t)(t + 4) * CC];
        float v5 = vp[(size_t)(t + 5) * CC];
        float v6 = vp[(size_t)(t + 6) * CC];
        float v7 = vp[(size_t)(t + 7) * CC];
        acc += s[t] * v0 + s[t + 1] * v1 + s[t + 2] * v2 + s[t + 3] * v3;
        acc += s[t + 4] * v4 + s[t + 5] * v5 + s[t + 6] * v6 + s[t + 7] * v7;
    }
    const int idx = (b * HH + h) * NCH + c;
    g_po[idx * HD + tid] = acc;
    if (tid == 0) { g_pm[idx] = mx; g_pl[idx] = sum; }
}

// combine -> bf16 hi/lo activations (input of proj GEMM)
__global__ __launch_bounds__(128) void attn_combine(const int* __restrict__ pos) {
    const int bh = blockIdx.x;
    const int b = bh >> 4, h = bh & 15;
    const int nch = (pos[b] >> 7) + 1;
    const int tid = threadIdx.x;
    float gm = -3.4e38f;
    for (int c = 0; c < nch; c++) gm = fmaxf(gm, g_pm[bh * NCH + c]);
    float l = 0.f, acc = 0.f;
    for (int c = 0; c < nch; c++) {
        const float w = __expf(g_pm[bh * NCH + c] - gm);
        l += g_pl[bh * NCH + c] * w;
        acc += g_po[(bh * NCH + c) * HD + tid] * w;
    }
    const float val = acc / l;
    const int di = b * CC + h * HD + tid;
    const __nv_bfloat16 hb = __float2bfloat16_rn(val);
    g_ah[di] = hb;
    g_al[di] = __float2bfloat16_rn(val - __bfloat162float(hb));
}

// ---------------- launch: kernel launches ONLY ----------------
extern "C" void kernel_launch(void* const* d_in, const int* in_sizes, int n_in,
                              void* d_out, int out_size) {
    const float* x           = (const float*)d_in[0];
    const float* prev_k      = (const float*)d_in[1];
    const float* prev_v      = (const float*)d_in[2];
    const int*   pos         = (const int*)d_in[3];
    const float* ln1_scale   = (const float*)d_in[4];
    const float* ln1_bias    = (const float*)d_in[5];
    const float* w_attn      = (const float*)d_in[6];
    const float* b_attn      = (const float*)d_in[7];
    const float* w_attn_proj = (const float*)d_in[8];
    const float* b_attn_proj = (const float*)d_in[9];
    const float* ln2_scale   = (const float*)d_in[10];
    const float* ln2_bias    = (const float*)d_in[11];
    const float* w_fc        = (const float*)d_in[12];
    const float* b_fc        = (const float*)d_in[13];
    const float* w_mlp_proj  = (const float*)d_in[14];
    const float* b_mlp_proj  = (const float*)d_in[15];
    float* out = (float*)d_out;   // [x | k_new | v_new]

    // 0-2. LN1 in 3 launches (puts gemm_tc(qkv) at launch idx 3 for ncu)
    ln_kernel<<<11, 256>>>(x, 0, 0, ln1_scale, ln1_bias);
    ln_kernel<<<11, 256>>>(x, 0, 11, ln1_scale, ln1_bias);
    ln_kernel<<<10, 256>>>(x, 0, 22, ln1_scale, ln1_bias);
    // 3. qkv GEMM: K=2048, N=6144; 24 n-blocks x 16 k-chunks(128) = 384 blocks
    gemm_tc<<<dim3(24, 16), 256, SM_GEMM>>>(w_attn, 2048, 6144, 128);
    // 4. reduce qkv: bias + scatter q / k_new / v_new (16 chunks)
    red_qkv<<<192, 256>>>(b_attn, out + 65536, out + 131072);
    // 5-6. attention
    attn_partial<<<dim3(NCH, HH, BB), 128>>>(prev_k, prev_v, pos);
    attn_combine<<<BB * HH, 128>>>(pos);
    // 7. attn proj GEMM: K=2048, N=2048; 8 x 32 k-chunks(64) = 256 blocks
    gemm_tc<<<dim3(8, 32), 256, SM_GEMM>>>(w_attn_proj, 2048, 2048, 64);
    // 8. reduce: bias + resid(x) -> g_x1 (32 chunks)
    red_resid<<<64, 256>>>(b_attn_proj, x, 0, nullptr, 1, 32);
    // 9. LN2: g_x1 -> hi/lo
    ln_kernel<<<32, 256>>>(nullptr, 1, 0, ln2_scale, ln2_bias);
    // 10. fc GEMM: K=2048, N=8192; 32 x 16 k-chunks(128) = 512 blocks
    gemm_tc<<<dim3(32, 16), 256, SM_GEMM>>>(w_fc, 2048, 8192, 128);
    // 11. reduce: bias + gelu -> hi/lo (16 chunks)
    red_gelu<<<256, 256>>>(b_fc);
    // 12. mlp proj GEMM: K=8192, N=2048; 8 x 64 k-chunks(128) = 512 blocks
    gemm_tc<<<dim3(8, 64), 256, SM_GEMM>>>(w_mlp_proj, 8192, 2048, 128);
    // 13. reduce: bias + resid(g_x1) -> out (64 chunks)
    red_resid<<<64, 256>>>(b_mlp_proj, nullptr, 1, out, 0, 64);
}